// round 5
// baseline (speedup 1.0000x reference)
#include <cuda_runtime.h>

// score[i] = sigmoid(logits[u[i] * V + v[i]]), V = 8192, B = 16384.
// Floor-test variant: 8192 threads (64 x 128), 2 elems/thread via int2,
// no bounds branch, 32-bit addressing (V*V = 2^26 fits in int), so the
// index LDGs issue immediately after the prologue.
__global__ void __launch_bounds__(128, 16)
topos_gather_sigmoid2(const int2* __restrict__ u2,
                      const int2* __restrict__ v2,
                      const float* __restrict__ logits,
                      float2* __restrict__ out2) {
    int i = blockIdx.x * 128 + threadIdx.x;

    int2 u = __ldg(&u2[i]);
    int2 v = __ldg(&v2[i]);

    // Two independent gathers, 32-bit address math (u < 8192 -> u<<13 < 2^26)
    float x0 = __ldg(logits + ((u.x << 13) | v.x));
    float x1 = __ldg(logits + ((u.y << 13) | v.y));

    float2 r;
    r.x = 1.0f / (1.0f + __expf(-x0));
    r.y = 1.0f / (1.0f + __expf(-x1));
    out2[i] = r;
}

extern "C" void kernel_launch(void* const* d_in, const int* in_sizes, int n_in,
                              void* d_out, int out_size) {
    const int2* u2 = (const int2*)d_in[0];
    const int2* v2 = (const int2*)d_in[1];
    const float* logits = (const float*)d_in[2];
    float2* out2 = (float2*)d_out;

    const int B = in_sizes[0];          // 16384
    const int threads = 128;
    const int blocks = (B / 2) / threads;  // 64
    topos_gather_sigmoid2<<<blocks, threads>>>(u2, v2, logits, out2);
}

// round 6
// speedup vs baseline: 1.1556x; 1.1556x over previous
#include <cuda_runtime.h>

// score[i] = sigmoid(logits[u[i] * V + v[i]]), V = 8192, B = 16384.
// Latency-floor kernel: scalar gather, 256 blocks x 64 threads (fastest
// measured shape), 32-bit addressing, fast-path sigmoid (__expf + MUFU.RCP
// via __fdividef) so no full-precision div subroutine sits on the drain path.
__global__ void __launch_bounds__(64, 32)
topos_gather_sigmoid(const int* __restrict__ u,
                     const int* __restrict__ v,
                     const float* __restrict__ logits,
                     float* __restrict__ out) {
    int i = blockIdx.x * 64 + threadIdx.x;
    int ui = __ldg(&u[i]);
    int vi = __ldg(&v[i]);
    float x = __ldg(logits + ((ui << 13) | vi));
    out[i] = __fdividef(1.0f, 1.0f + __expf(-x));
}

extern "C" void kernel_launch(void* const* d_in, const int* in_sizes, int n_in,
                              void* d_out, int out_size) {
    const int* u = (const int*)d_in[0];
    const int* v = (const int*)d_in[1];
    const float* logits = (const float*)d_in[2];
    float* out = (float*)d_out;

    const int B = in_sizes[0];  // 16384, multiple of 64
    topos_gather_sigmoid<<<B / 64, 64>>>(u, v, logits, out);
}